// round 5
// baseline (speedup 1.0000x reference)
#include <cuda_runtime.h>
#include <cstdint>

#define BATCH   4096
#define IN_DIM  512
#define OUT_DIM 512
#define NG      8      // GRID_SIZE + K = 5 + 3
// B-spline: 12 knots, uniform h = 0.4, grid[n] = -1 + 0.4*n

// ---------------- scratch (no allocs allowed) ----------------
__device__ float g_Wt[IN_DIM * NG * OUT_DIM];        // [(i*8+g)][j]   8 MB
__device__ float g_basisT[(size_t)IN_DIM * BATCH * NG]; // [i][b][g]  64 MB

// ---------------- f32x2 helpers ----------------
__device__ __forceinline__ unsigned long long ffma2(unsigned long long a,
                                                    unsigned long long b,
                                                    unsigned long long c) {
    unsigned long long d;
    asm("fma.rn.f32x2 %0, %1, %2, %3;" : "=l"(d) : "l"(a), "l"(b), "l"(c));
    return d;
}
__device__ __forceinline__ unsigned long long pack2(float lo, float hi) {
    unsigned long long d;
    asm("mov.b64 %0, {%1, %2};" : "=l"(d) : "f"(lo), "f"(hi));
    return d;
}
__device__ __forceinline__ void unpack2(unsigned long long v, float& lo, float& hi) {
    asm("mov.b64 {%0, %1}, %2;" : "=f"(lo), "=f"(hi) : "l"(v));
}

// ---------------- 1) W' = coeff * scaling, transposed to [(i,g)][j] ----------------
__global__ void build_wt(const float* __restrict__ coeff,
                         const float* __restrict__ scaling) {
    int j = blockIdx.x * blockDim.x + threadIdx.x;   // 0..511
    int i = blockIdx.y;                              // 0..511
    float s = scaling[i * OUT_DIM + j];
    const float4* c4 =
        reinterpret_cast<const float4*>(coeff + ((size_t)i * OUT_DIM + j) * NG);
    float4 a = c4[0], b = c4[1];
    float v[8] = {a.x, a.y, a.z, a.w, b.x, b.y, b.z, b.w};
#pragma unroll
    for (int g = 0; g < 8; g++)
        g_Wt[(i * 8 + g) * OUT_DIM + j] = v[g] * s;   // coalesced per g
}

// ---------------- 2) basisT[i][b][g] via de Boor (uniform grid) ----------------
__global__ void build_basis(const float* __restrict__ x) {
    int b = blockIdx.y * blockDim.x + threadIdx.x;   // 0..4095
    int i = blockIdx.x;                              // 0..511
    float xv = x[(size_t)b * IN_DIM + i];

    float grid[12];
#pragma unroll
    for (int n = 0; n < 12; n++) grid[n] = -1.0f + 0.4f * (float)n;

    float B[11];
#pragma unroll
    for (int t = 0; t < 11; t++)
        B[t] = (grid[t] <= xv && xv < grid[t + 1]) ? 1.0f : 0.0f;

    // denominators are d*h (uniform grid) -> constant reciprocals, no div
    const float inv1 = 2.5f;         // 1/(0.4)
    const float inv2 = 1.25f;        // 1/(0.8)
    const float inv3 = 0.83333333f;  // 1/(1.2)
#pragma unroll
    for (int t = 0; t < 10; t++)
        B[t] = (xv - grid[t]) * inv1 * B[t] + (grid[t + 2] - xv) * inv1 * B[t + 1];
#pragma unroll
    for (int t = 0; t < 9; t++)
        B[t] = (xv - grid[t]) * inv2 * B[t] + (grid[t + 3] - xv) * inv2 * B[t + 1];
#pragma unroll
    for (int t = 0; t < 8; t++)
        B[t] = (xv - grid[t]) * inv3 * B[t] + (grid[t + 4] - xv) * inv3 * B[t + 1];

    float* dst = g_basisT + ((size_t)i * BATCH + b) * NG;  // b-contiguous: coalesced
    reinterpret_cast<float4*>(dst)[0] = make_float4(B[0], B[1], B[2], B[3]);
    reinterpret_cast<float4*>(dst)[1] = make_float4(B[4], B[5], B[6], B[7]);
}

// ---------------- 3) GEMM: out[64x128 tile] += basis * W', FFMA2 inner loop ----------------
#define BM 64
#define BN 128
#define BSTR 132   // 132 floats = 528B, 16B-aligned rows; reads are broadcast so bank-safe

__global__ __launch_bounds__(256, 2)
void kan_gemm(float* __restrict__ out) {
    __shared__ float sW[2][8][BN];     // W' K-slab:  [g][j]        8 KB
    __shared__ float sBd[2][8][BSTR];  // basis dup:  [g][2r]=(v,v) 8.25 KB

    const int tid  = threadIdx.x;
    const int lane = tid & 31;
    const int warp = tid >> 5;          // 8 warps; warp handles rows r0..r0+7
    const int r0   = warp * 8;
    const int jbase = blockIdx.x * BN;
    const int bbase = blockIdx.y * BM;

    const int wrow = tid >> 5;          // 0..7  (g index for W loader)
    const int wcol = (tid & 31) * 4;    // 0..124

    unsigned long long acc[8][2];
#pragma unroll
    for (int r = 0; r < 8; r++) { acc[r][0] = 0ull; acc[r][1] = 0ull; }

    // ---- prologue: stage i = 0 into buffer 0 ----
    {
        float4 rw = *reinterpret_cast<const float4*>(
            &g_Wt[(0 * 8 + wrow) * OUT_DIM + jbase + wcol]);
        *reinterpret_cast<float4*>(&sW[0][wrow][wcol]) = rw;
        if (tid < 64) {
            const float4* bs = reinterpret_cast<const float4*>(
                &g_basisT[((size_t)0 * BATCH + bbase + tid) * NG]);
            float4 b0 = bs[0], b1 = bs[1];
            float vv[8] = {b0.x, b0.y, b0.z, b0.w, b1.x, b1.y, b1.z, b1.w};
#pragma unroll
            for (int g = 0; g < 8; g++) {
                float2 p = make_float2(vv[g], vv[g]);
                *reinterpret_cast<float2*>(&sBd[0][g][2 * tid]) = p;
            }
        }
    }
    __syncthreads();

    float4 rw;
    float4 rb0 = make_float4(0.f, 0.f, 0.f, 0.f);
    float4 rb1 = make_float4(0.f, 0.f, 0.f, 0.f);

    for (int i = 0; i < IN_DIM; i++) {
        const int buf = i & 1;
        const bool has_next = (i + 1 < IN_DIM);

        // prefetch next K-slab into registers (overlaps with compute)
        if (has_next) {
            rw = *reinterpret_cast<const float4*>(
                &g_Wt[((i + 1) * 8 + wrow) * OUT_DIM + jbase + wcol]);
            if (tid < 64) {
                const float4* bs = reinterpret_cast<const float4*>(
                    &g_basisT[((size_t)(i + 1) * BATCH + bbase + tid) * NG]);
                rb0 = bs[0];
                rb1 = bs[1];
            }
        }

        // ---- compute: 128 FFMA2 (= 256 FMA) per thread ----
#pragma unroll
        for (int g = 0; g < 8; g++) {
            float4 wv = *reinterpret_cast<const float4*>(&sW[buf][g][lane * 4]);
            unsigned long long w01 = pack2(wv.x, wv.y);
            unsigned long long w23 = pack2(wv.z, wv.w);

            // duplicated basis: float4 = (v_r, v_r, v_{r+1}, v_{r+1}) -> two b64 operands
            float4 q0 = *reinterpret_cast<const float4*>(&sBd[buf][g][2 * r0 + 0]);
            float4 q1 = *reinterpret_cast<const float4*>(&sBd[buf][g][2 * r0 + 4]);
            float4 q2 = *reinterpret_cast<const float4*>(&sBd[buf][g][2 * r0 + 8]);
            float4 q3 = *reinterpret_cast<const float4*>(&sBd[buf][g][2 * r0 + 12]);
            unsigned long long bb[8];
            bb[0] = pack2(q0.x, q0.y); bb[1] = pack2(q0.z, q0.w);
            bb[2] = pack2(q1.x, q1.y); bb[3] = pack2(q1.z, q1.w);
            bb[4] = pack2(q2.x, q2.y); bb[5] = pack2(q2.z, q2.w);
            bb[6] = pack2(q3.x, q3.y); bb[7] = pack2(q3.z, q3.w);

#pragma unroll
            for (int r = 0; r < 8; r++) {
                acc[r][0] = ffma2(bb[r], w01, acc[r][0]);
                acc[r][1] = ffma2(bb[r], w23, acc[r][1]);
            }
        }

        // ---- stage next slab into the other buffer (safe: old reads of it
        //      were fenced by the previous iteration's barrier) ----
        if (has_next) {
            const int nb = buf ^ 1;
            *reinterpret_cast<float4*>(&sW[nb][wrow][wcol]) = rw;
            if (tid < 64) {
                float vv[8] = {rb0.x, rb0.y, rb0.z, rb0.w, rb1.x, rb1.y, rb1.z, rb1.w};
#pragma unroll
                for (int g = 0; g < 8; g++) {
                    float2 p = make_float2(vv[g], vv[g]);
                    *reinterpret_cast<float2*>(&sBd[nb][g][2 * tid]) = p;
                }
            }
        }
        __syncthreads();
    }

    // ---- epilogue: unpack and store (fully coalesced float4) ----
#pragma unroll
    for (int r = 0; r < 8; r++) {
        float v0, v1, v2, v3;
        unpack2(acc[r][0], v0, v1);
        unpack2(acc[r][1], v2, v3);
        *reinterpret_cast<float4*>(
            &out[(size_t)(bbase + r0 + r) * OUT_DIM + jbase + lane * 4]) =
            make_float4(v0, v1, v2, v3);
    }
}

// ---------------- launch ----------------
extern "C" void kernel_launch(void* const* d_in, const int* in_sizes, int n_in,
                              void* d_out, int out_size) {
    const float* x       = (const float*)d_in[0];   // [4096, 512]
    const float* coeff   = (const float*)d_in[1];   // [512, 512, 8]
    const float* scaling = (const float*)d_in[2];   // [512, 512]
    float* out           = (float*)d_out;           // [4096, 512]
    (void)in_sizes; (void)n_in; (void)out_size;

    build_wt<<<dim3(OUT_DIM / 256, IN_DIM), 256>>>(coeff, scaling);
    build_basis<<<dim3(IN_DIM, BATCH / 256), 256>>>(x);
    kan_gemm<<<dim3(OUT_DIM / BN, BATCH / BM), 256>>>(out);
}

// round 8
// speedup vs baseline: 2.1640x; 2.1640x over previous
#include <cuda_runtime.h>
#include <cuda_bf16.h>
#include <cstdint>

#define BATCH   4096
#define IN_DIM  512
#define OUT_DIM 512
#define NG      8
#define KDIM    4096   // IN_DIM * NG
#define NC      128    // K chunks of 32
#define STAGE   32768  // {Ah,Al,Bh,Bl} x (128 x 32 bf16 = 8KB)

// ---------------- scratch: bf16 hi/lo split operands ----------------
__device__ __align__(128) __nv_bfloat16 g_Ahi[(size_t)BATCH * KDIM];   // 32 MB [b][k]
__device__ __align__(128) __nv_bfloat16 g_Alo[(size_t)BATCH * KDIM];   // 32 MB
__device__ __align__(128) __nv_bfloat16 g_Bhi[(size_t)OUT_DIM * KDIM]; // 4 MB  [j][k]
__device__ __align__(128) __nv_bfloat16 g_Blo[(size_t)OUT_DIM * KDIM]; // 4 MB

__device__ __forceinline__ uint32_t cvta_shared(const void* p) {
    uint32_t a;
    asm("{ .reg .u64 t; cvta.to.shared.u64 t, %1; cvt.u32.u64 %0, t; }"
        : "=r"(a) : "l"(p));
    return a;
}

// ---------------- 1) basis -> bf16 hi/lo, A[b][i*8+g] ----------------
__global__ void build_basis(const float* __restrict__ x) {
    int i = blockIdx.x * 256 + threadIdx.x;   // 0..511
    int b = blockIdx.y;                       // 0..4095
    float xv = x[(size_t)b * IN_DIM + i];

    float grid[12];
#pragma unroll
    for (int n = 0; n < 12; n++) grid[n] = -1.0f + 0.4f * (float)n;

    float B[11];
#pragma unroll
    for (int t = 0; t < 11; t++)
        B[t] = (grid[t] <= xv && xv < grid[t + 1]) ? 1.0f : 0.0f;

    const float inv1 = 2.5f, inv2 = 1.25f, inv3 = 0.83333333f;
#pragma unroll
    for (int t = 0; t < 10; t++)
        B[t] = (xv - grid[t]) * inv1 * B[t] + (grid[t + 2] - xv) * inv1 * B[t + 1];
#pragma unroll
    for (int t = 0; t < 9; t++)
        B[t] = (xv - grid[t]) * inv2 * B[t] + (grid[t + 3] - xv) * inv2 * B[t + 1];
#pragma unroll
    for (int t = 0; t < 8; t++)
        B[t] = (xv - grid[t]) * inv3 * B[t] + (grid[t + 4] - xv) * inv3 * B[t + 1];

    uint32_t wh[4], wl[4];
#pragma unroll
    for (int p = 0; p < 4; p++) {
        __nv_bfloat16 h0 = __float2bfloat16_rn(B[2 * p]);
        __nv_bfloat16 h1 = __float2bfloat16_rn(B[2 * p + 1]);
        __nv_bfloat16 l0 = __float2bfloat16_rn(B[2 * p]     - __bfloat162float(h0));
        __nv_bfloat16 l1 = __float2bfloat16_rn(B[2 * p + 1] - __bfloat162float(h1));
        wh[p] = (uint32_t)__bfloat16_as_ushort(h0) | ((uint32_t)__bfloat16_as_ushort(h1) << 16);
        wl[p] = (uint32_t)__bfloat16_as_ushort(l0) | ((uint32_t)__bfloat16_as_ushort(l1) << 16);
    }
    size_t o = ((size_t)b * KDIM + i * 8);
    *reinterpret_cast<uint4*>(&g_Ahi[o]) = make_uint4(wh[0], wh[1], wh[2], wh[3]);
    *reinterpret_cast<uint4*>(&g_Alo[o]) = make_uint4(wl[0], wl[1], wl[2], wl[3]);
}

// ---------------- 2) W = coeff*scaling, transposed to [j][i*8+g], hi/lo ----------------
__global__ void build_wt(const float* __restrict__ coeff,
                         const float* __restrict__ scaling) {
    __shared__ float s[32][260];
    int i0 = blockIdx.x * 32, j0 = blockIdx.y * 32;
    for (int l = threadIdx.x; l < 8192; l += 256) {
        int ii = l >> 8, jg = l & 255;
        s[ii][jg] = coeff[(size_t)(i0 + ii) * (OUT_DIM * NG) + j0 * 8 + jg];
    }
    __syncthreads();
    for (int l = threadIdx.x; l < 8192; l += 256) {
        int j = l >> 8, ig = l & 255, ii = ig >> 3, g = ig & 7;
        float v = s[ii][j * 8 + g] * scaling[(size_t)(i0 + ii) * OUT_DIM + j0 + j];
        __nv_bfloat16 h = __float2bfloat16_rn(v);
        float r = v - __bfloat162float(h);
        size_t o = (size_t)(j0 + j) * KDIM + (i0 + ii) * 8 + g;
        g_Bhi[o] = h;
        g_Blo[o] = __float2bfloat16_rn(r);
    }
}

// ---------------- 3) HMMA GEMM (mma.sync m16n8k16 bf16, 3-pass split) ----------------
// CTA 128x128 tile, 8 warps = 4(m) x 2(n): warp tile 32(m) x 64(n).
// smem tile: 128 rows x 32 k bf16 (64B/row = 4x16B chunks). Swizzle: physical
// chunk = r*4 + (q ^ ((r>>1)&3))  -> conflict-free ldmatrix + cp.async.

__device__ __forceinline__ void ldm4(uint32_t& r0, uint32_t& r1, uint32_t& r2,
                                     uint32_t& r3, uint32_t addr) {
    asm volatile("ldmatrix.sync.aligned.m8n8.x4.shared.b16 {%0,%1,%2,%3}, [%4];"
                 : "=r"(r0), "=r"(r1), "=r"(r2), "=r"(r3) : "r"(addr));
}

#define MMA(d, a, b)                                                         \
    asm volatile(                                                            \
        "mma.sync.aligned.m16n8k16.row.col.f32.bf16.bf16.f32 "               \
        "{%0,%1,%2,%3}, {%4,%5,%6,%7}, {%8,%9}, {%0,%1,%2,%3};"              \
        : "+f"((d)[0]), "+f"((d)[1]), "+f"((d)[2]), "+f"((d)[3])             \
        : "r"((a)[0]), "r"((a)[1]), "r"((a)[2]), "r"((a)[3]),                \
          "r"((b)[0]), "r"((b)[1]))

__global__ __launch_bounds__(256, 1) void kan_mma(float* __restrict__ out) {
    extern __shared__ char dyn[];
    const uint32_t sb = cvta_shared(dyn);

    const int tid = threadIdx.x, wid = tid >> 5, lane = tid & 31;
    const int jbase = blockIdx.x * 128, bbase = blockIdx.y * 128;
    const int m0 = (wid & 3) * 32, n0 = (wid >> 2) * 64;

    const __nv_bfloat16* src[4];
    src[0] = g_Ahi + (size_t)bbase * KDIM;
    src[1] = g_Alo + (size_t)bbase * KDIM;
    src[2] = g_Bhi + (size_t)jbase * KDIM;
    src[3] = g_Blo + (size_t)jbase * KDIM;

    // per-thread staging coords: chunk = v*256 + tid -> r = chunk>>2, q = chunk&3
#define ISSUE(c, st)                                                         \
    {                                                                        \
        _Pragma("unroll") for (int a = 0; a < 4; a++)                        \
            _Pragma("unroll") for (int v = 0; v < 2; v++) {                  \
                int ch = v * 256 + tid;                                      \
                int r = ch >> 2, q = ch & 3;                                 \
                const void* g = src[a] + (size_t)r * KDIM + (c) * 32 + q * 8; \
                uint32_t d = sb + (st) * STAGE + a * 8192 + r * 64 +         \
                             ((q ^ ((r >> 1) & 3)) << 4);                    \
                asm volatile("cp.async.cg.shared.global [%0], [%1], 16;"     \
                             :: "r"(d), "l"(g));                             \
            }                                                                \
        asm volatile("cp.async.commit_group;");                              \
    }

    float acc[2][8][4];
#pragma unroll
    for (int mi = 0; mi < 2; mi++)
#pragma unroll
        for (int nf = 0; nf < 8; nf++)
#pragma unroll
            for (int e = 0; e < 4; e++) acc[mi][nf][e] = 0.0f;

    // ldmatrix per-lane row/quad components (fixed per lane)
    const int laneA = lane & 15;                         // A: row offset
    const int qA    = lane >> 4;                         // A: k-half select
    const int rBl   = (lane & 7) + ((lane >> 4) << 3);   // B: row offset
    const int qB    = (lane >> 3) & 1;                   // B: k-half select

    ISSUE(0, 0);

    for (int c = 0; c < NC; c++) {
        const int s = c & 1;
        asm volatile("cp.async.wait_group 0;" ::: "memory");
        __syncthreads();                       // stage s visible; stage s^1 free
        if (c + 1 < NC) ISSUE(c + 1, s ^ 1);   // prefetch overlaps compute

        const uint32_t stg = sb + s * STAGE;
#pragma unroll
        for (int ks = 0; ks < 2; ks++) {
            const int q0 = ks * 2;
            uint32_t ah[2][4], al[2][4];
#pragma unroll
            for (int mi = 0; mi < 2; mi++) {
                int r = m0 + mi * 16 + laneA;
                int q = q0 + qA;
                uint32_t sw = r * 64 + ((q ^ ((r >> 1) & 3)) << 4);
                ldm4(ah[mi][0], ah[mi][1], ah[mi][2], ah[mi][3], stg + sw);
                ldm4(al[mi][0], al[mi][1], al[mi][2], al[mi][3], stg + 8192 + sw);
            }
            uint32_t bh[8][2], bl[8][2];
#pragma unroll
            for (int g = 0; g < 4; g++) {
                int r = n0 + g * 16 + rBl;
                int q = q0 + qB;
                uint32_t sw = r * 64 + ((q ^ ((r >> 1) & 3)) << 4);
                ldm4(bh[2 * g][0], bh[2 * g][1], bh[2 * g + 1][0], bh[2 * g + 1][1],
                     stg + 16384 + sw);
                ldm4(bl[2 * g][0], bl[2 * g][1], bl[2 * g + 1][0], bl[2 * g + 1][1],
                     stg + 24576 + sw);
            }
#pragma unroll
            for (int mi = 0; mi < 2; mi++)
#pragma unroll
                for (int nf = 0; nf < 8; nf++) {
                    MMA(acc[mi][nf], ah[mi], bh[nf]);   // Ah*Bh
                    MMA(acc[mi][nf], ah[mi], bl[nf]);   // Ah*Bl
                    MMA(acc[mi][nf], al[mi], bh[nf]);   // Al*Bh
                }
        }
    }

    // ---- epilogue: direct float2 stores ----
    const int row  = lane >> 2;
    const int colp = (lane & 3) * 2;
#pragma unroll
    for (int mi = 0; mi < 2; mi++)
#pragma unroll
        for (int nf = 0; nf < 8; nf++) {
            size_t r0o = (size_t)(bbase + m0 + mi * 16 + row) * OUT_DIM +
                         jbase + n0 + nf * 8 + colp;
            *reinterpret_cast<float2*>(&out[r0o]) =
                make_float2(acc[mi][nf][0], acc[mi][nf][1]);
            *reinterpret_cast<float2*>(&out[r0o + 8 * OUT_DIM]) =
                make_float2(acc[mi][nf][2], acc[mi][nf][3]);
        }
}

// ---------------- launch ----------------
extern "C" void kernel_launch(void* const* d_in, const int* in_sizes, int n_in,
                              void* d_out, int out_size) {
    const float* x       = (const float*)d_in[0];   // [4096, 512]
    const float* coeff   = (const float*)d_in[1];   // [512, 512, 8]
    const float* scaling = (const float*)d_in[2];   // [512, 512]
    float* out           = (float*)d_out;           // [4096, 512]
    (void)in_sizes; (void)n_in; (void)out_size;

    cudaFuncSetAttribute(kan_mma, cudaFuncAttributeMaxDynamicSharedMemorySize,
                         2 * STAGE);

    build_basis<<<dim3(IN_DIM / 256, BATCH), 256>>>(x);
    build_wt<<<dim3(IN_DIM / 32, OUT_DIM / 32), 256>>>(coeff, scaling);
    kan_mma<<<dim3(OUT_DIM / 128, BATCH / 128), 256, 2 * STAGE>>>(out);
}

// round 12
// speedup vs baseline: 3.6477x; 1.6857x over previous
#include <cuda_runtime.h>
#include <cuda_bf16.h>
#include <cstdint>

#define BATCH   4096
#define IN_DIM  512
#define OUT_DIM 512
#define NG      8
#define KDIM    4096   // IN_DIM * NG
#define KC      64     // K elems per chunk (128B rows)
#define NC      (KDIM / KC)          // 64 chunks
#define ARR     16384                // one operand tile: 128 rows x 128B
#define STAGE   (4 * ARR)            // {Ah,Al,Bh,Bl} = 64KB

// ---------------- scratch: bf16 hi/lo split operands ----------------
__device__ __align__(128) __nv_bfloat16 g_Ahi[(size_t)BATCH * KDIM];   // 32 MB [b][k]
__device__ __align__(128) __nv_bfloat16 g_Alo[(size_t)BATCH * KDIM];   // 32 MB
__device__ __align__(128) __nv_bfloat16 g_Bhi[(size_t)OUT_DIM * KDIM]; // 4 MB  [j][k]
__device__ __align__(128) __nv_bfloat16 g_Blo[(size_t)OUT_DIM * KDIM]; // 4 MB

__device__ __forceinline__ uint32_t cvta_shared(const void* p) {
    uint32_t a;
    asm("{ .reg .u64 t; cvta.to.shared.u64 t, %1; cvt.u32.u64 %0, t; }"
        : "=r"(a) : "l"(p));
    return a;
}

// ---------------- 1) basis via closed-form uniform cubic B-spline ----------------
// For x in cell c (= floor((x+1)/h), h=0.4), nonzero bases are g = c-3..c with
// weights {(1-t)^3, 3t^3-6t^2+4, -3t^3+3t^2+3t+1, t^3}/6 (t = local coord).
// Out-of-range g (<0) simply drop — matches the reference's truncated recursion.
__global__ void build_basis(const float* __restrict__ x) {
    int i = blockIdx.x * 256 + threadIdx.x;   // 0..511
    int b = blockIdx.y;                       // 0..4095
    float xv = x[(size_t)b * IN_DIM + i];

    float u  = (xv + 1.0f) * 2.5f;
    float cf = floorf(u);
    cf = fminf(fmaxf(cf, 0.0f), 4.0f);
    int   c  = (int)cf;
    float t  = u - cf;

    float t2 = t * t, t3 = t2 * t;
    float omt = 1.0f - t;
    const float s6 = 1.0f / 6.0f;
    float w[4];
    w[0] = omt * omt * omt * s6;                          // g = c-3
    w[1] = (3.0f * t3 - 6.0f * t2 + 4.0f) * s6;           // g = c-2
    w[2] = (-3.0f * t3 + 3.0f * t2 + 3.0f * t + 1.0f) * s6; // g = c-1
    w[3] = t3 * s6;                                       // g = c

    float B[8];
#pragma unroll
    for (int g = 0; g < 8; g++) {
        int d = g - c + 3;   // 0..3 -> valid weight
        float v = 0.0f;
        v = (d == 0) ? w[0] : v;
        v = (d == 1) ? w[1] : v;
        v = (d == 2) ? w[2] : v;
        v = (d == 3) ? w[3] : v;
        B[g] = v;
    }

    uint32_t wh[4], wl[4];
#pragma unroll
    for (int p = 0; p < 4; p++) {
        __nv_bfloat16 h0 = __float2bfloat16_rn(B[2 * p]);
        __nv_bfloat16 h1 = __float2bfloat16_rn(B[2 * p + 1]);
        __nv_bfloat16 l0 = __float2bfloat16_rn(B[2 * p]     - __bfloat162float(h0));
        __nv_bfloat16 l1 = __float2bfloat16_rn(B[2 * p + 1] - __bfloat162float(h1));
        wh[p] = (uint32_t)__bfloat16_as_ushort(h0) | ((uint32_t)__bfloat16_as_ushort(h1) << 16);
        wl[p] = (uint32_t)__bfloat16_as_ushort(l0) | ((uint32_t)__bfloat16_as_ushort(l1) << 16);
    }
    size_t o = ((size_t)b * KDIM + i * 8);
    *reinterpret_cast<uint4*>(&g_Ahi[o]) = make_uint4(wh[0], wh[1], wh[2], wh[3]);
    *reinterpret_cast<uint4*>(&g_Alo[o]) = make_uint4(wl[0], wl[1], wl[2], wl[3]);
}

// ---------------- 2) W = coeff*scaling, transposed to [j][i*8+g], hi/lo ----------------
__global__ void build_wt(const float* __restrict__ coeff,
                         const float* __restrict__ scaling) {
    __shared__ float s[32][260];
    int i0 = blockIdx.x * 32, j0 = blockIdx.y * 32;
    for (int l = threadIdx.x; l < 8192; l += 256) {
        int ii = l >> 8, jg = l & 255;
        s[ii][jg] = coeff[(size_t)(i0 + ii) * (OUT_DIM * NG) + j0 * 8 + jg];
    }
    __syncthreads();
    for (int l = threadIdx.x; l < 8192; l += 256) {
        int j = l >> 8, ig = l & 255, ii = ig >> 3, g = ig & 7;
        float v = s[ii][j * 8 + g] * scaling[(size_t)(i0 + ii) * OUT_DIM + j0 + j];
        __nv_bfloat16 h = __float2bfloat16_rn(v);
        float r = v - __bfloat162float(h);
        size_t o = (size_t)(j0 + j) * KDIM + (i0 + ii) * 8 + g;
        g_Bhi[o] = h;
        g_Blo[o] = __float2bfloat16_rn(r);
    }
}

// ---------------- 3) HMMA GEMM: 512 threads, warp tile 32x32, 3-pass split ----------------
// smem row = 128B (KC=64 bf16), swizzle: 16B-chunk q -> q ^ (r & 7).

__device__ __forceinline__ void ldm4(uint32_t& r0, uint32_t& r1, uint32_t& r2,
                                     uint32_t& r3, uint32_t addr) {
    asm volatile("ldmatrix.sync.aligned.m8n8.x4.shared.b16 {%0,%1,%2,%3}, [%4];"
                 : "=r"(r0), "=r"(r1), "=r"(r2), "=r"(r3) : "r"(addr));
}

#define MMA(d, a, b)                                                         \
    asm volatile(                                                            \
        "mma.sync.aligned.m16n8k16.row.col.f32.bf16.bf16.f32 "               \
        "{%0,%1,%2,%3}, {%4,%5,%6,%7}, {%8,%9}, {%0,%1,%2,%3};"              \
        : "+f"((d)[0]), "+f"((d)[1]), "+f"((d)[2]), "+f"((d)[3])             \
        : "r"((a)[0]), "r"((a)[1]), "r"((a)[2]), "r"((a)[3]),                \
          "r"((b)[0]), "r"((b)[1]))

__global__ __launch_bounds__(512, 1) void kan_mma(float* __restrict__ out) {
    extern __shared__ char dyn[];
    const uint32_t sb = cvta_shared(dyn);

    const int tid = threadIdx.x, wid = tid >> 5, lane = tid & 31;
    const int jbase = blockIdx.x * 128, bbase = blockIdx.y * 128;
    const int m0 = (wid & 3) * 32, n0 = (wid >> 2) * 32;  // 4m x 4n warp grid

    const __nv_bfloat16* src[4];
    src[0] = g_Ahi + (size_t)bbase * KDIM;
    src[1] = g_Alo + (size_t)bbase * KDIM;
    src[2] = g_Bhi + (size_t)jbase * KDIM;
    src[3] = g_Blo + (size_t)jbase * KDIM;

    // staging: per array 1024 16B-units; 512 threads x 2
#define ISSUE(c, st)                                                          \
    {                                                                         \
        _Pragma("unroll") for (int a = 0; a < 4; a++)                         \
            _Pragma("unroll") for (int v = 0; v < 2; v++) {                   \
                int ch = v * 512 + tid;                                       \
                int r = ch >> 3, q = ch & 7;                                  \
                const void* g = src[a] + (size_t)r * KDIM + (c) * KC + q * 8; \
                uint32_t d = sb + (st) * STAGE + a * ARR + r * 128 +          \
                             ((q ^ (r & 7)) << 4);                            \
                asm volatile("cp.async.cg.shared.global [%0], [%1], 16;"      \
                             :: "r"(d), "l"(g));                              \
            }                                                                 \
        asm volatile("cp.async.commit_group;");                               \
    }

    float acc[2][4][4];
#pragma unroll
    for (int mi = 0; mi < 2; mi++)
#pragma unroll
        for (int nf = 0; nf < 4; nf++)
#pragma unroll
            for (int e = 0; e < 4; e++) acc[mi][nf][e] = 0.0f;

    const int laneA = lane & 15;                         // A: row offset
    const int qA    = lane >> 4;                         // A: 16B k-half
    const int rBl   = (lane & 7) + ((lane >> 4) << 3);   // B: row offset
    const int qB    = (lane >> 3) & 1;                   // B: 16B k-half

    ISSUE(0, 0);

    for (int c = 0; c < NC; c++) {
        const int s = c & 1;
        asm volatile("cp.async.wait_group 0;" ::: "memory");
        __syncthreads();                       // stage s visible; stage s^1 free
        if (c + 1 < NC) ISSUE(c + 1, s ^ 1);   // prefetch overlaps compute

        const uint32_t stg = sb + s * STAGE;
#pragma unroll
        for (int ks = 0; ks < 4; ks++) {       // 4 x k16 per 64-chunk
            const int q0 = ks * 2;
            uint32_t ah[2][4], al[2][4];
#pragma unroll
            for (int mi = 0; mi < 2; mi++) {
                int r = m0 + mi * 16 + laneA;
                int q = q0 + qA;
                uint32_t sw = r * 128 + ((q ^ (r & 7)) << 4);
                ldm4(ah[mi][0], ah[mi][1], ah[mi][2], ah[mi][3], stg + sw);
                ldm4(al[mi][0], al[mi][1], al[mi][2], al[mi][3], stg + ARR + sw);
            }
            uint32_t bh[4][2], bl[4][2];
#pragma unroll
            for (int g = 0; g < 2; g++) {
                int r = n0 + g * 16 + rBl;
                int q = q0 + qB;
                uint32_t sw = r * 128 + ((q ^ (r & 7)) << 4);
                ldm4(bh[2 * g][0], bh[2 * g][1], bh[2 * g + 1][0], bh[2 * g + 1][1],
                     stg + 2 * ARR + sw);
                ldm4(bl[2 * g][0], bl[2 * g][1], bl[2 * g + 1][0], bl[2 * g + 1][1],
                     stg + 3 * ARR + sw);
            }
            // pass-outer ordering: 8 independent accs between reuses
#pragma unroll
            for (int mi = 0; mi < 2; mi++)
#pragma unroll
                for (int nf = 0; nf < 4; nf++) MMA(acc[mi][nf], ah[mi], bh[nf]);
#pragma unroll
            for (int mi = 0; mi < 2; mi++)
#pragma unroll
                for (int nf = 0; nf < 4; nf++) MMA(acc[mi][nf], ah[mi], bl[nf]);
#pragma unroll
            for (int mi = 0; mi < 2; mi++)
#pragma unroll
                for (int nf = 0; nf < 4; nf++) MMA(acc[mi][nf], al[mi], bh[nf]);
        }
    }

    // ---- epilogue: direct float2 stores ----
    const int row  = lane >> 2;
    const int colp = (lane & 3) * 2;
#pragma unroll
    for (int mi = 0; mi < 2; mi++)
#pragma unroll
        for (int nf = 0; nf < 4; nf++) {
            size_t r0o = (size_t)(bbase + m0 + mi * 16 + row) * OUT_DIM +
                         jbase + n0 + nf * 8 + colp;
            *reinterpret_cast<float2*>(&out[r0o]) =
                make_float2(acc[mi][nf][0], acc[mi][nf][1]);
            *reinterpret_cast<float2*>(&out[r0o + 8 * OUT_DIM]) =
                make_float2(acc[mi][nf][2], acc[mi][nf][3]);
        }
}

// ---------------- launch ----------------
extern "C" void kernel_launch(void* const* d_in, const int* in_sizes, int n_in,
                              void* d_out, int out_size) {
    const float* x       = (const float*)d_in[0];   // [4096, 512]
    const float* coeff   = (const float*)d_in[1];   // [512, 512, 8]
    const float* scaling = (const float*)d_in[2];   // [512, 512]
    float* out           = (float*)d_out;           // [4096, 512]
    (void)in_sizes; (void)n_in; (void)out_size;

    cudaFuncSetAttribute(kan_mma, cudaFuncAttributeMaxDynamicSharedMemorySize,
                         2 * STAGE);

    build_basis<<<dim3(IN_DIM / 256, BATCH), 256>>>(x);
    build_wt<<<dim3(IN_DIM / 32, OUT_DIM / 32), 256>>>(coeff, scaling);
    kan_mma<<<dim3(OUT_DIM / 128, BATCH / 128), 512, 2 * STAGE>>>(out);
}

// round 13
// speedup vs baseline: 7.8247x; 2.1451x over previous
#include <cuda_runtime.h>
#include <cuda_fp16.h>
#include <cstdint>

#define BATCH   4096
#define IN_DIM  512
#define OUT_DIM 512
#define NG      8
#define KDIM    4096   // IN_DIM * NG
#define KC      64     // K elems per chunk (128B fp16 rows)
#define NC      (KDIM / KC)      // 64 chunks
#define ARR     16384            // one operand tile: 128 rows x 128B
#define STAGE   (2 * ARR)        // {A, B} = 32KB
#define NSTAGE  3
#define DSMEM   (NSTAGE * STAGE) // 96KB

// ---------------- scratch: fp16 operands ----------------
__device__ __align__(128) __half g_A[(size_t)BATCH * KDIM];    // 32MB... (fp16: 32MB? 4096*4096*2 = 32MB) [b][k]
__device__ __align__(128) __half g_B[(size_t)OUT_DIM * KDIM];  // 4MB [j][k]

__device__ __forceinline__ uint32_t cvta_shared(const void* p) {
    uint32_t a;
    asm("{ .reg .u64 t; cvta.to.shared.u64 t, %1; cvt.u32.u64 %0, t; }"
        : "=r"(a) : "l"(p));
    return a;
}

// ---------------- 1) basis via closed-form uniform cubic B-spline (fp16 out) ----------------
// x in cell c = clamp(floor((x+1)*2.5), 0, 4); nonzero bases g = c-3..c with
// weights {(1-t)^3, 3t^3-6t^2+4, -3t^3+3t^2+3t+1, t^3}/6. Out-of-range g drop.
__global__ void build_basis(const float* __restrict__ x) {
    int i = blockIdx.x * 256 + threadIdx.x;   // 0..511
    int b = blockIdx.y;                       // 0..4095
    float xv = x[(size_t)b * IN_DIM + i];

    float u  = (xv + 1.0f) * 2.5f;
    float cf = floorf(u);
    cf = fminf(fmaxf(cf, 0.0f), 4.0f);
    int   c  = (int)cf;
    float t  = u - cf;

    float t2 = t * t, t3 = t2 * t;
    float omt = 1.0f - t;
    const float s6 = 1.0f / 6.0f;
    uint16_t hw0 = __half_as_ushort(__float2half_rn(omt * omt * omt * s6));
    uint16_t hw1 = __half_as_ushort(__float2half_rn((3.0f * t3 - 6.0f * t2 + 4.0f) * s6));
    uint16_t hw2 = __half_as_ushort(__float2half_rn((-3.0f * t3 + 3.0f * t2 + 3.0f * t + 1.0f) * s6));
    uint16_t hw3 = __half_as_ushort(__float2half_rn(t3 * s6));

    uint32_t r[4];
#pragma unroll
    for (int p = 0; p < 4; p++) {
        int d0 = 2 * p - c + 3, d1 = d0 + 1;
        uint32_t lo = (d0 == 0) ? hw0 : (d0 == 1) ? hw1 : (d0 == 2) ? hw2 : (d0 == 3) ? hw3 : 0;
        uint32_t hi = (d1 == 0) ? hw0 : (d1 == 1) ? hw1 : (d1 == 2) ? hw2 : (d1 == 3) ? hw3 : 0;
        r[p] = lo | (hi << 16);
    }
    *reinterpret_cast<uint4*>(&g_A[(size_t)b * KDIM + i * 8]) =
        make_uint4(r[0], r[1], r[2], r[3]);
}

// ---------------- 2) W = coeff*scaling, transposed to [j][i*8+g], fp16 ----------------
__global__ void build_wt(const float* __restrict__ coeff,
                         const float* __restrict__ scaling) {
    __shared__ float s[32][260];
    int i0 = blockIdx.x * 32, j0 = blockIdx.y * 32;
    for (int l = threadIdx.x; l < 8192; l += 256) {
        int ii = l >> 8, jg = l & 255;
        s[ii][jg] = coeff[(size_t)(i0 + ii) * (OUT_DIM * NG) + j0 * 8 + jg];
    }
    __syncthreads();
    for (int l = threadIdx.x; l < 8192; l += 256) {
        int j = l >> 8, ig = l & 255, ii = ig >> 3, g = ig & 7;
        float v = s[ii][j * 8 + g] * scaling[(size_t)(i0 + ii) * OUT_DIM + j0 + j];
        g_B[(size_t)(j0 + j) * KDIM + (i0 + ii) * 8 + g] = __float2half_rn(v);
    }
}

// ---------------- 3) HMMA GEMM: 512 threads, warp tile 32x32, single fp16 pass ----------------
__device__ __forceinline__ void ldm4(uint32_t& r0, uint32_t& r1, uint32_t& r2,
                                     uint32_t& r3, uint32_t addr) {
    asm volatile("ldmatrix.sync.aligned.m8n8.x4.shared.b16 {%0,%1,%2,%3}, [%4];"
                 : "=r"(r0), "=r"(r1), "=r"(r2), "=r"(r3) : "r"(addr));
}

#define MMA(d, a, b)                                                         \
    asm volatile(                                                            \
        "mma.sync.aligned.m16n8k16.row.col.f32.f16.f16.f32 "                 \
        "{%0,%1,%2,%3}, {%4,%5,%6,%7}, {%8,%9}, {%0,%1,%2,%3};"              \
        : "+f"((d)[0]), "+f"((d)[1]), "+f"((d)[2]), "+f"((d)[3])             \
        : "r"((a)[0]), "r"((a)[1]), "r"((a)[2]), "r"((a)[3]),                \
          "r"((b)[0]), "r"((b)[1]))

__global__ __launch_bounds__(512, 1) void kan_mma(float* __restrict__ out) {
    extern __shared__ char dyn[];
    const uint32_t sb = cvta_shared(dyn);

    const int tid = threadIdx.x, wid = tid >> 5, lane = tid & 31;
    const int jbase = blockIdx.x * 128, bbase = blockIdx.y * 128;
    const int m0 = (wid & 3) * 32, n0 = (wid >> 2) * 32;  // 4m x 4n warp grid

    const __half* srcA = g_A + (size_t)bbase * KDIM;
    const __half* srcB = g_B + (size_t)jbase * KDIM;

    // staging: per array 1024 16B-units; 512 threads x 2
#define ISSUE(c, st)                                                          \
    {                                                                         \
        _Pragma("unroll") for (int a = 0; a < 2; a++)                         \
            _Pragma("unroll") for (int v = 0; v < 2; v++) {                   \
                int ch = v * 512 + tid;                                       \
                int r = ch >> 3, q = ch & 7;                                  \
                const __half* base = a ? srcB : srcA;                         \
                const void* g = base + (size_t)r * KDIM + (c) * KC + q * 8;   \
                uint32_t d = sb + (st) * STAGE + a * ARR + r * 128 +          \
                             ((q ^ (r & 7)) << 4);                            \
                asm volatile("cp.async.cg.shared.global [%0], [%1], 16;"      \
                             :: "r"(d), "l"(g));                              \
            }                                                                 \
        asm volatile("cp.async.commit_group;");                               \
    }

    float acc[2][4][4];
#pragma unroll
    for (int mi = 0; mi < 2; mi++)
#pragma unroll
        for (int nf = 0; nf < 4; nf++)
#pragma unroll
            for (int e = 0; e < 4; e++) acc[mi][nf][e] = 0.0f;

    const int laneA = lane & 15;                         // A: row offset
    const int qA    = lane >> 4;                         // A: 16B k-half
    const int rBl   = (lane & 7) + ((lane >> 4) << 3);   // B: row offset
    const int qB    = (lane >> 3) & 1;                   // B: 16B k-half

    ISSUE(0, 0);
    ISSUE(1, 1);

    for (int c = 0; c < NC; c++) {
        if (c + 1 < NC)
            asm volatile("cp.async.wait_group 1;" ::: "memory");   // chunk c landed
        else
            asm volatile("cp.async.wait_group 0;" ::: "memory");   // last chunk
        __syncthreads();                   // publish stage; slot (c+2)%3 free
        if (c + 2 < NC) ISSUE(c + 2, (c + 2) % 3);

        const uint32_t stg = sb + (c % 3) * STAGE;
#pragma unroll
        for (int ks = 0; ks < 4; ks++) {   // 4 x k16 per 64-chunk
            const int q0 = ks * 2;
            uint32_t ah[2][4];
#pragma unroll
            for (int mi = 0; mi < 2; mi++) {
                int r = m0 + mi * 16 + laneA;
                int q = q0 + qA;
                uint32_t sw = r * 128 + ((q ^ (r & 7)) << 4);
                ldm4(ah[mi][0], ah[mi][1], ah[mi][2], ah[mi][3], stg + sw);
            }
            uint32_t bh[4][2];
#pragma unroll
            for (int g = 0; g < 2; g++) {
                int r = n0 + g * 16 + rBl;
                int q = q0 + qB;
                uint32_t sw = r * 128 + ((q ^ (r & 7)) << 4);
                ldm4(bh[2 * g][0], bh[2 * g][1], bh[2 * g + 1][0], bh[2 * g + 1][1],
                     stg + ARR + sw);
            }
#pragma unroll
            for (int mi = 0; mi < 2; mi++)
#pragma unroll
                for (int nf = 0; nf < 4; nf++) MMA(acc[mi][nf], ah[mi], bh[nf]);
        }
    }

    // ---- epilogue: direct float2 stores ----
    const int row  = lane >> 2;
    const int colp = (lane & 3) * 2;
#pragma unroll
    for (int mi = 0; mi < 2; mi++)
#pragma unroll
        for (int nf = 0; nf < 4; nf++) {
            size_t r0o = (size_t)(bbase + m0 + mi * 16 + row) * OUT_DIM +
                         jbase + n0 + nf * 8 + colp;
            *reinterpret_cast<float2*>(&out[r0o]) =
                make_float2(acc[mi][nf][0], acc[mi][nf][1]);
            *reinterpret_cast<float2*>(&out[r0o + 8 * OUT_DIM]) =
                make_float2(acc[mi][nf][2], acc[mi][nf][3]);
        }
}

// ---------------- launch ----------------
extern "C" void kernel_launch(void* const* d_in, const int* in_sizes, int n_in,
                              void* d_out, int out_size) {
    const float* x       = (const float*)d_in[0];   // [4096, 512]
    const float* coeff   = (const float*)d_in[1];   // [512, 512, 8]
    const float* scaling = (const float*)d_in[2];   // [512, 512]
    float* out           = (float*)d_out;           // [4096, 512]
    (void)in_sizes; (void)n_in; (void)out_size;

    cudaFuncSetAttribute(kan_mma, cudaFuncAttributeMaxDynamicSharedMemorySize,
                         DSMEM);

    build_basis<<<dim3(IN_DIM / 256, BATCH), 256>>>(x);
    build_wt<<<dim3(IN_DIM / 32, OUT_DIM / 32), 256>>>(coeff, scaling);
    kan_mma<<<dim3(OUT_DIM / 128, BATCH / 128), 512, DSMEM>>>(out);
}